// round 7
// baseline (speedup 1.0000x reference)
#include <cuda_runtime.h>
#include <cstddef>
#include <math.h>

// ---------------- problem constants ----------------
constexpr int FV  = 92;
constexpr int FE  = 41;
constexpr int NL  = 3;
constexpr int NG  = 256;
constexpr int NMAX = 50000;
constexpr int MMAX = 800000;

// ---------------- device scratch (16B+ alignment required for float4 / red.v4) ----------------
__device__ alignas(128) float g_v[NMAX * 64];            // node features (current)
__device__ alignas(128) float g_P[NMAX * 256];           // [src-gate|src-scr|dst-gate|dst-scr]
__device__ alignas(128) float g_Y[(size_t)MMAX * 128];   // per-edge pre-BN activations
__device__ alignas(128) float g_agg[NMAX * 64];          // scattered messages / emb scratch
__device__ alignas(128) float g_Wcat[FE * 384];          // packed W3 (rows 128..168) all layers
__device__ alignas(128) float g_Wnode[NL * 64 * 256];    // packed node weights per layer
__device__ alignas(128) float g_stats[256];              // [sum | sumsq]
__device__ alignas(128) float g_mean[128];
__device__ alignas(128) float g_rstd[128];
__device__ alignas(128) float g_pool[NG * 64];
__device__ alignas(128) float g_cntf[NG];
__device__ alignas(128) float g_fc0[NG * 128];
__device__ alignas(128) float g_fc1[NG * 64];

// ---------------- helpers ----------------
__device__ __forceinline__ float sigm_(float x) { return 1.f / (1.f + __expf(-x)); }
__device__ __forceinline__ float silu_(float x) { return x / (1.f + __expf(-x)); }
__device__ __forceinline__ float sp_(float x)   { return fmaxf(x, 0.f) + log1pf(__expf(-fabsf(x))); }

__device__ __forceinline__ void red_add_v4(float* p, float a, float b, float c, float d) {
    asm volatile("red.global.add.v4.f32 [%0], {%1, %2, %3, %4};"
                 :: "l"(p), "f"(a), "f"(b), "f"(c), "f"(d) : "memory");
}

static inline int cdiv(int a, int b) { return (a + b - 1) / b; }

// ---------------- weight repack ----------------
// g_Wcat[k*384 + l*128 + cc]  : cc<64 -> Wm[l,128+k,cc], else Ws[l,128+k,cc-64]
// g_Wnode[l*16384 + k*256 + c]: blk=c>>7, cc=c&127, row = blk?64+k:k,
//                               cc<64 -> Wm[l,row,cc] else Ws[l,row,cc-64]
__global__ void repack_kernel(const float* __restrict__ Wm, const float* __restrict__ Ws) {
    const int total1 = FE * 384;
    const int total2 = NL * 64 * 256;
    for (int idx = blockIdx.x * blockDim.x + threadIdx.x; idx < total1 + total2;
         idx += gridDim.x * blockDim.x) {
        if (idx < total1) {
            int k = idx / 384, c = idx - k * 384;
            int l = c >> 7, cc = c & 127;
            const float* W = (cc & 64) ? Ws : Wm;
            g_Wcat[idx] = W[((size_t)l * 169 + 128 + k) * 64 + (cc & 63)];
        } else {
            int j = idx - total1;
            int l = j / (64 * 256);
            int rem = j - l * 64 * 256;
            int k = rem >> 8, c = rem & 255;
            int blk = c >> 7, cc = c & 127;
            const float* W = (cc & 64) ? Ws : Wm;
            int row = blk ? (64 + k) : k;
            g_Wnode[j] = W[((size_t)l * 169 + row) * 64 + (cc & 63)];
        }
    }
}

// ---------------- generic tiled fp32 GEMM: C[M,*] = A[M,K] @ B[K,ldb] ----------------
template <int BM, int BN, int KT, int TM, int TN>
__global__ void __launch_bounds__(256)
gemm_f32(const float* __restrict__ A, const float* __restrict__ B,
         float* __restrict__ C, int M, int K, int ldb, int ldc) {
    __shared__ alignas(16) float As[BM * KT];   // [m][kk]
    __shared__ alignas(16) float Bs[KT * BN];   // [kk][c]
    const int m0 = blockIdx.y * BM;
    const int nb = blockIdx.x * BN;
    const int tid = threadIdx.x;
    const int tx = tid % (BN / TN);
    const int ty = tid / (BN / TN);

    float acc[TM][TN];
#pragma unroll
    for (int i = 0; i < TM; i++)
#pragma unroll
        for (int j = 0; j < TN; j++) acc[i][j] = 0.f;

    for (int k0 = 0; k0 < K; k0 += KT) {
        for (int idx = tid; idx < BM * KT; idx += 256) {
            int m = idx / KT, kk = idx - m * KT;
            int gm = m0 + m, gk = k0 + kk;
            As[idx] = (gm < M && gk < K) ? A[(size_t)gm * K + gk] : 0.f;
        }
        for (int idx = tid; idx < KT * BN; idx += 256) {
            int kk = idx / BN, c = idx - kk * BN;
            int gk = k0 + kk;
            Bs[idx] = (gk < K) ? B[(size_t)gk * ldb + nb + c] : 0.f;
        }
        __syncthreads();

#pragma unroll
        for (int kk4 = 0; kk4 < KT / 4; ++kk4) {
            float4 a4[TM];
            float4 b4[4];
#pragma unroll
            for (int i = 0; i < TM; i++)
                a4[i] = *(const float4*)(As + (ty * TM + i) * KT + kk4 * 4);
#pragma unroll
            for (int jk = 0; jk < 4; jk++)
                b4[jk] = *(const float4*)(Bs + (kk4 * 4 + jk) * BN + tx * TN);
#pragma unroll
            for (int jk = 0; jk < 4; jk++) {
                float4 bj = b4[jk];
#pragma unroll
                for (int i = 0; i < TM; i++) {
                    float ai = (jk == 0) ? a4[i].x : (jk == 1) ? a4[i].y
                             : (jk == 2) ? a4[i].z : a4[i].w;
                    acc[i][0] = fmaf(ai, bj.x, acc[i][0]);
                    acc[i][1] = fmaf(ai, bj.y, acc[i][1]);
                    acc[i][2] = fmaf(ai, bj.z, acc[i][2]);
                    acc[i][3] = fmaf(ai, bj.w, acc[i][3]);
                }
            }
        }
        __syncthreads();
    }

#pragma unroll
    for (int i = 0; i < TM; ++i) {
        int m = m0 + ty * TM + i;
        if (m < M) {
            float4 r = make_float4(acc[i][0], acc[i][1], acc[i][2], acc[i][3]);
            *(float4*)(C + (size_t)m * ldc + nb + tx * TN) = r;
        }
    }
}

// ---------------- zero ----------------
__global__ void zero_f(float* p, int n) {
    for (int i = blockIdx.x * blockDim.x + threadIdx.x; i < n; i += gridDim.x * blockDim.x)
        p[i] = 0.f;
}
__global__ void zero4(float4* p, int n4) {
    for (int i = blockIdx.x * blockDim.x + threadIdx.x; i < n4; i += gridDim.x * blockDim.x)
        p[i] = make_float4(0.f, 0.f, 0.f, 0.f);
}

// ---------------- BN helpers ----------------
__global__ void finalize_kernel(int C, float inv) {
    int c = threadIdx.x;
    if (c < C) {
        float m = g_stats[c] * inv;
        float v = g_stats[C + c] * inv - m * m;
        g_mean[c] = m;
        g_rstd[c] = rsqrtf(v + 1e-5f);
    }
}

// per-channel sum/sumsq over X[rows, C]  (C in {64,128}), accumulates into g_stats
__global__ void stats_kernel(const float* __restrict__ X, int rows, int C) {
    __shared__ float sbuf[256];
    int tid = threadIdx.x;
    for (int i = tid; i < 2 * C; i += blockDim.x) sbuf[i] = 0.f;
    __syncthreads();
    int cpr = C >> 2;  // threads per row (each handles 4 channels)
    int c = (tid % cpr) * 4;
    int r = (blockIdx.x * blockDim.x + tid) / cpr;
    int stride = (gridDim.x * blockDim.x) / cpr;
    float s0 = 0, s1 = 0, s2 = 0, s3 = 0, q0 = 0, q1 = 0, q2 = 0, q3 = 0;
    for (; r < rows; r += stride) {
        float4 x = *(const float4*)(X + (size_t)r * C + c);
        s0 += x.x; s1 += x.y; s2 += x.z; s3 += x.w;
        q0 += x.x * x.x; q1 += x.y * x.y; q2 += x.z * x.z; q3 += x.w * x.w;
    }
    atomicAdd(&sbuf[c + 0], s0); atomicAdd(&sbuf[c + 1], s1);
    atomicAdd(&sbuf[c + 2], s2); atomicAdd(&sbuf[c + 3], s3);
    atomicAdd(&sbuf[C + c + 0], q0); atomicAdd(&sbuf[C + c + 1], q1);
    atomicAdd(&sbuf[C + c + 2], q2); atomicAdd(&sbuf[C + c + 3], q3);
    __syncthreads();
    for (int i = tid; i < 2 * C; i += blockDim.x) atomicAdd(&g_stats[i], sbuf[i]);
}

// Y = silu(bn(X)) over [rows, C]
__global__ void bn_silu(const float* __restrict__ X, float* __restrict__ Y, int rows, int C,
                        const float* __restrict__ gamma, const float* __restrict__ beta) {
    int tid = blockIdx.x * blockDim.x + threadIdx.x;
    int cpr = C >> 2;
    int c = (tid % cpr) * 4;
    int r = tid / cpr;
    int stride = (gridDim.x * blockDim.x) / cpr;
    float mm[4], rr[4], ga[4], bb[4];
#pragma unroll
    for (int i = 0; i < 4; i++) {
        mm[i] = g_mean[c + i]; rr[i] = g_rstd[c + i];
        ga[i] = gamma[c + i]; bb[i] = beta[c + i];
    }
    for (; r < rows; r += stride) {
        float4 x = *(const float4*)(X + (size_t)r * C + c);
        float o[4] = {x.x, x.y, x.z, x.w};
#pragma unroll
        for (int i = 0; i < 4; i++) o[i] = silu_((o[i] - mm[i]) * rr[i] * ga[i] + bb[i]);
        *(float4*)(Y + (size_t)r * C + c) = make_float4(o[0], o[1], o[2], o[3]);
    }
}

// ---------------- edge pass 1 (fused edge-feature GEMM + gather + stats) ----------------
// y[e,cc] = sum_k ef[e,k]*Wcat[k, l*128+cc] + P[src[e], cc] + P[dst[e], 128+cc]
// g_Y written with streaming hint (evict-first) to keep g_P resident in L2.
__global__ void __launch_bounds__(256)
edge_pass1(const float* __restrict__ ef, const int* __restrict__ src,
           const int* __restrict__ dst, int M, int l) {
    __shared__ alignas(16) float Wsm[FE * 128];
    __shared__ float ssum[128], ssq[128];
    int tid = threadIdx.x;
    for (int idx = tid; idx < FE * 128; idx += blockDim.x) {
        int k = idx >> 7, c = idx & 127;
        Wsm[idx] = g_Wcat[k * 384 + l * 128 + c];
    }
    if (tid < 128) { ssum[tid] = 0.f; ssq[tid] = 0.f; }
    __syncthreads();

    int lane = tid & 31;
    int warp = (blockIdx.x * blockDim.x + tid) >> 5;
    int nw = (gridDim.x * blockDim.x) >> 5;
    int c4 = lane * 4;
    float s[4] = {0, 0, 0, 0}, q[4] = {0, 0, 0, 0};

    for (int e0 = warp * 4; e0 < M; e0 += nw * 4) {
        int eN = M - e0; if (eN > 4) eN = 4;
        int ei1 = e0 + (eN > 1 ? 1 : 0);
        int ei2 = e0 + (eN > 2 ? 2 : 0);
        int ei3 = e0 + (eN > 3 ? 3 : 0);
        const float* p0 = ef + (size_t)e0 * FE;
        const float* p1 = ef + (size_t)ei1 * FE;
        const float* p2 = ef + (size_t)ei2 * FE;
        const float* p3 = ef + (size_t)ei3 * FE;

        float acc[4][4];
#pragma unroll
        for (int i = 0; i < 4; i++)
#pragma unroll
            for (int j = 0; j < 4; j++) acc[i][j] = 0.f;

        for (int k = 0; k < FE; ++k) {
            float4 w4 = *(const float4*)(Wsm + k * 128 + c4);
            float a0 = __ldg(p0 + k), a1 = __ldg(p1 + k), a2 = __ldg(p2 + k), a3 = __ldg(p3 + k);
            acc[0][0] = fmaf(a0, w4.x, acc[0][0]); acc[0][1] = fmaf(a0, w4.y, acc[0][1]);
            acc[0][2] = fmaf(a0, w4.z, acc[0][2]); acc[0][3] = fmaf(a0, w4.w, acc[0][3]);
            acc[1][0] = fmaf(a1, w4.x, acc[1][0]); acc[1][1] = fmaf(a1, w4.y, acc[1][1]);
            acc[1][2] = fmaf(a1, w4.z, acc[1][2]); acc[1][3] = fmaf(a1, w4.w, acc[1][3]);
            acc[2][0] = fmaf(a2, w4.x, acc[2][0]); acc[2][1] = fmaf(a2, w4.y, acc[2][1]);
            acc[2][2] = fmaf(a2, w4.z, acc[2][2]); acc[2][3] = fmaf(a2, w4.w, acc[2][3]);
            acc[3][0] = fmaf(a3, w4.x, acc[3][0]); acc[3][1] = fmaf(a3, w4.y, acc[3][1]);
            acc[3][2] = fmaf(a3, w4.z, acc[3][2]); acc[3][3] = fmaf(a3, w4.w, acc[3][3]);
        }

#pragma unroll
        for (int ei = 0; ei < 4; ei++) {
            if (ei < eN) {
                int e = e0 + ei;
                int sN = src[e], dN = dst[e];
                float4 pa = *(const float4*)(g_P + (size_t)sN * 256 + c4);
                float4 pb = *(const float4*)(g_P + (size_t)dN * 256 + 128 + c4);
                float y0 = acc[ei][0] + pa.x + pb.x;
                float y1 = acc[ei][1] + pa.y + pb.y;
                float y2 = acc[ei][2] + pa.z + pb.z;
                float y3 = acc[ei][3] + pa.w + pb.w;
                __stcs((float4*)(g_Y + (size_t)e * 128 + c4),
                       make_float4(y0, y1, y2, y3));
                s[0] += y0; s[1] += y1; s[2] += y2; s[3] += y3;
                q[0] += y0 * y0; q[1] += y1 * y1; q[2] += y2 * y2; q[3] += y3 * y3;
            }
        }
    }
#pragma unroll
    for (int i = 0; i < 4; i++) {
        atomicAdd(&ssum[c4 + i], s[i]);
        atomicAdd(&ssq[c4 + i], q[i]);
    }
    __syncthreads();
    if (tid < 128) {
        atomicAdd(&g_stats[tid], ssum[tid]);
        atomicAdd(&g_stats[128 + tid], ssq[tid]);
    }
}

// ---------------- edge pass 2: BN + sigmoid/softplus + product + scatter ----------------
// g_Y read with streaming hint; scatter target g_agg stays L2-resident.
__global__ void edge_pass2(const int* __restrict__ dst, int M,
                           const float* __restrict__ gml, const float* __restrict__ beml,
                           const float* __restrict__ gsl, const float* __restrict__ besl) {
    int t = blockIdx.x * blockDim.x + threadIdx.x;
    int c = (t & 15) * 4;
    int stride = (gridDim.x * blockDim.x) >> 4;
    float mm[4], rm[4], ga[4], ba[4], ms[4], rs[4], gb[4], bb[4];
#pragma unroll
    for (int i = 0; i < 4; i++) {
        mm[i] = g_mean[c + i];      rm[i] = g_rstd[c + i];
        ga[i] = gml[c + i];         ba[i] = beml[c + i];
        ms[i] = g_mean[64 + c + i]; rs[i] = g_rstd[64 + c + i];
        gb[i] = gsl[c + i];         bb[i] = besl[c + i];
    }
    for (int e = t >> 4; e < M; e += stride) {
        float4 ym = __ldcs((const float4*)(g_Y + (size_t)e * 128 + c));
        float4 ys = __ldcs((const float4*)(g_Y + (size_t)e * 128 + 64 + c));
        float m0 = sigm_((ym.x - mm[0]) * rm[0] * ga[0] + ba[0]);
        float m1 = sigm_((ym.y - mm[1]) * rm[1] * ga[1] + ba[1]);
        float m2 = sigm_((ym.z - mm[2]) * rm[2] * ga[2] + ba[2]);
        float m3 = sigm_((ym.w - mm[3]) * rm[3] * ga[3] + ba[3]);
        float s0 = sp_((ys.x - ms[0]) * rs[0] * gb[0] + bb[0]);
        float s1 = sp_((ys.y - ms[1]) * rs[1] * gb[1] + bb[1]);
        float s2 = sp_((ys.z - ms[2]) * rs[2] * gb[2] + bb[2]);
        float s3 = sp_((ys.w - ms[3]) * rs[3] * gb[3] + bb[3]);
        int d = dst[e];
        red_add_v4(g_agg + (size_t)d * 64 + c, m0 * s0, m1 * s1, m2 * s2, m3 * s3);
    }
}

// ---------------- node update: v = softplus(bn(agg)*gn+ben + v) ----------------
__global__ void node_update(int N, const float* __restrict__ gnl, const float* __restrict__ benl) {
    int t = blockIdx.x * blockDim.x + threadIdx.x;
    int c = (t & 15) * 4;
    int stride = (gridDim.x * blockDim.x) >> 4;
    float mm[4], rr[4], ga[4], bb[4];
#pragma unroll
    for (int i = 0; i < 4; i++) {
        mm[i] = g_mean[c + i]; rr[i] = g_rstd[c + i];
        ga[i] = gnl[c + i]; bb[i] = benl[c + i];
    }
    for (int n = t >> 4; n < N; n += stride) {
        float4 a = *(const float4*)(g_agg + (size_t)n * 64 + c);
        float4 v = *(const float4*)(g_v + (size_t)n * 64 + c);
        float o0 = sp_((a.x - mm[0]) * rr[0] * ga[0] + bb[0] + v.x);
        float o1 = sp_((a.y - mm[1]) * rr[1] * ga[1] + bb[1] + v.y);
        float o2 = sp_((a.z - mm[2]) * rr[2] * ga[2] + bb[2] + v.z);
        float o3 = sp_((a.w - mm[3]) * rr[3] * ga[3] + bb[3] + v.w);
        *(float4*)(g_v + (size_t)n * 64 + c) = make_float4(o0, o1, o2, o3);
    }
}

// ---------------- pooling ----------------
__global__ void pool_scatter(const int* __restrict__ gid, int N) {
    int t = blockIdx.x * blockDim.x + threadIdx.x;
    int c = (t & 15) * 4;
    int stride = (gridDim.x * blockDim.x) >> 4;
    for (int n = t >> 4; n < N; n += stride) {
        int g = gid[n];
        float4 x = *(const float4*)(g_v + (size_t)n * 64 + c);
        red_add_v4(g_pool + (size_t)g * 64 + c, x.x, x.y, x.z, x.w);
        if ((t & 15) == 0)
            asm volatile("red.global.add.f32 [%0], %1;" :: "l"(g_cntf + g), "f"(1.0f) : "memory");
    }
}
__global__ void pool_div() {
    int t = blockIdx.x * blockDim.x + threadIdx.x;
    if (t < NG * 16) {
        int g = t >> 4, c = (t & 15) * 4;
        float inv = 1.f / fmaxf(g_cntf[g], 1.f);
        float4 x = *(const float4*)(g_pool + g * 64 + c);
        *(float4*)(g_pool + g * 64 + c) = make_float4(x.x * inv, x.y * inv, x.z * inv, x.w * inv);
    }
}

// ---------------- regression head ----------------
__global__ void head_kernel(const float* __restrict__ Wt, const float* __restrict__ bt,
                            float* __restrict__ out) {
    int g = blockIdx.x * blockDim.x + threadIdx.x;
    if (g < NG) {
        float s = bt[0];
#pragma unroll
        for (int k = 0; k < 64; k++) s = fmaf(g_fc1[g * 64 + k], Wt[k], s);
        out[g] = s;
    }
}

// ---------------- launch ----------------
extern "C" void kernel_launch(void* const* d_in, const int* in_sizes, int n_in,
                              void* d_out, int out_size) {
    const float* node_feats = (const float*)d_in[0];
    const float* edge_feats = (const float*)d_in[1];
    const int*   src        = (const int*)d_in[2];
    const int*   dst        = (const int*)d_in[3];
    const int*   gid        = (const int*)d_in[4];
    const float* W_emb = (const float*)d_in[5];
    const float* g_emb = (const float*)d_in[7];
    const float* be_emb = (const float*)d_in[8];
    const float* Wm  = (const float*)d_in[9];
    const float* gm  = (const float*)d_in[11];
    const float* bem = (const float*)d_in[12];
    const float* Ws  = (const float*)d_in[13];
    const float* gs  = (const float*)d_in[15];
    const float* bes = (const float*)d_in[16];
    const float* gn  = (const float*)d_in[17];
    const float* ben = (const float*)d_in[18];
    const float* Wf0 = (const float*)d_in[19];
    const float* gf0 = (const float*)d_in[21];
    const float* bef0 = (const float*)d_in[22];
    const float* Wf1 = (const float*)d_in[23];
    const float* gf1 = (const float*)d_in[25];
    const float* bef1 = (const float*)d_in[26];
    const float* Wt = (const float*)d_in[27];
    const float* bt = (const float*)d_in[28];
    float* out = (float*)d_out;

    const int N = in_sizes[0] / FV;
    const int M = in_sizes[2];

    // device symbol addresses (host-side queries, graph-capture-safe)
    float *p_v, *p_P, *p_agg, *p_Wnode, *p_stats, *p_pool, *p_cntf, *p_fc0, *p_fc1;
    cudaGetSymbolAddress((void**)&p_v, g_v);
    cudaGetSymbolAddress((void**)&p_P, g_P);
    cudaGetSymbolAddress((void**)&p_agg, g_agg);
    cudaGetSymbolAddress((void**)&p_Wnode, g_Wnode);
    cudaGetSymbolAddress((void**)&p_stats, g_stats);
    cudaGetSymbolAddress((void**)&p_pool, g_pool);
    cudaGetSymbolAddress((void**)&p_cntf, g_cntf);
    cudaGetSymbolAddress((void**)&p_fc0, g_fc0);
    cudaGetSymbolAddress((void**)&p_fc1, g_fc1);

    repack_kernel<<<128, 256>>>(Wm, Ws);

    // ---- embedding: v = silu(bn(node_feats @ W_emb)) ----
    zero_f<<<1, 256>>>(p_stats, 256);
    {
        dim3 grid(1, cdiv(N, 128));
        gemm_f32<128, 64, 16, 8, 4><<<grid, 256>>>(node_feats, W_emb, p_agg, N, FV, 64, 64);
    }
    stats_kernel<<<1024, 256>>>(p_agg, N, 64);
    finalize_kernel<<<1, 128>>>(64, 1.f / (float)N);
    bn_silu<<<1024, 256>>>(p_agg, p_v, N, 64, g_emb, be_emb);

    // ---- conv layers ----
    for (int l = 0; l < NL; ++l) {
        // node partial products: P = v @ Wnode[l]   [N,256]
        {
            dim3 grid(4, cdiv(N, 128));
            gemm_f32<128, 64, 16, 8, 4><<<grid, 256>>>(p_v, p_Wnode + l * 64 * 256, p_P,
                                                       N, 64, 256, 256);
        }
        // edge pass 1: fused edge GEMM + gather + stats
        zero_f<<<1, 256>>>(p_stats, 256);
        edge_pass1<<<2048, 256>>>(edge_feats, src, dst, M, l);
        finalize_kernel<<<1, 128>>>(128, 1.f / (float)M);
        // scatter target
        zero4<<<1024, 256>>>((float4*)p_agg, N * 16);
        edge_pass2<<<4096, 256>>>(dst, M, gm + l * 64, bem + l * 64, gs + l * 64, bes + l * 64);
        // node BN stats + update
        zero_f<<<1, 256>>>(p_stats, 256);
        stats_kernel<<<1024, 256>>>(p_agg, N, 64);
        finalize_kernel<<<1, 128>>>(64, 1.f / (float)N);
        node_update<<<1024, 256>>>(N, gn + l * 64, ben + l * 64);
    }

    // ---- pooling ----
    zero4<<<64, 256>>>((float4*)p_pool, NG * 16);
    zero_f<<<1, 256>>>(p_cntf, NG);
    pool_scatter<<<512, 256>>>(gid, N);
    pool_div<<<16, 256>>>();

    // ---- fc0: [256,64]@[64,128] ----
    {
        dim3 grid(2, 2);
        gemm_f32<128, 64, 16, 8, 4><<<grid, 256>>>(p_pool, Wf0, p_fc0, NG, 64, 128, 128);
    }
    zero_f<<<1, 256>>>(p_stats, 256);
    stats_kernel<<<32, 256>>>(p_fc0, NG, 128);
    finalize_kernel<<<1, 128>>>(128, 1.f / (float)NG);
    bn_silu<<<32, 256>>>(p_fc0, p_fc0, NG, 128, gf0, bef0);

    // ---- fc1: [256,128]@[128,64] ----
    {
        dim3 grid(1, 2);
        gemm_f32<128, 64, 16, 8, 4><<<grid, 256>>>(p_fc0, Wf1, p_fc1, NG, 128, 64, 64);
    }
    zero_f<<<1, 256>>>(p_stats, 256);
    stats_kernel<<<16, 256>>>(p_fc1, NG, 64);
    finalize_kernel<<<1, 128>>>(64, 1.f / (float)NG);
    bn_silu<<<16, 256>>>(p_fc1, p_fc1, NG, 64, gf1, bef1);

    // ---- head ----
    head_kernel<<<1, 256>>>(Wt, bt, out);
}